// round 14
// baseline (speedup 1.0000x reference)
#include <cuda_runtime.h>

// TransientCombNoise: B=32, T=2000, BLOCK=64, SR=16000, MAX_DELAY=480
// N = 64000 independent rows of 64 samples.
//
//   delay = int(32 + 32*bandwidth) in [33, 63]  =>  single FIR tap:
//       y[s] = x[s] + (s >= delay ? tilt * x[s-delay] : 0)
//   envelope exp(-s/a) = r^s via binary decomposition.
//   out = y * rsqrt(mean(y^2) + 1e-5)
//
// Layout: HALF-WARP per row, 4 samples per lane (float4):
//   - 1 LDG.128 + 1 STG.128 per 2 rows.
//   - params loaded DIRECTLY per pair (uniform per half, adjacent rows share
//     one 32B sector, L1-resident) -> zero broadcast shfls, no prologue.
//     Param pipeline (incl. __expf) recomputed per half: MUFU is per
//     warp-instruction, so 4 expf/warp is noise on an idle MUFU pipe.
//   - RMS reduce = 4 shfl_xor inside each 16-lane half (serves both rows).
//   - tap: component (k-dj)&3 uniform per half; index math hoisted.
//   8 shfls / 2 rows (was 12), inter-iteration ILP preserved.

#define N_ROWS (32 * 2000)
#define BATCH  8                  // rows per warp
#define NWARPS (N_ROWS / BATCH)   // 8000
#define FULLM  0xffffffffu

__global__ void __launch_bounds__(256)
transient_comb_kernel(const float4* __restrict__ params4, // [N] float4
                      const float4* __restrict__ noise4,  // [N*16] float4
                      float4*       __restrict__ out4)    // [N*16] float4
{
    const int warp = (blockIdx.x * blockDim.x + threadIdx.x) >> 5;
    const int lane = threadIdx.x & 31;
    if (warp >= NWARPS) return;

    const int base = warp * BATCH;
    const int h    = lane >> 4;       // half: 0 -> even row, 1 -> odd row
    const int hl   = lane & 15;       // sub-lane within half
    const int s0   = hl << 2;         // first sample index handled (0..60)

    // loop-invariant predicates for the r^(4*hl) decomposition
    const bool g1 = (hl & 1) != 0;
    const bool g2 = (hl & 2) != 0;
    const bool g4 = (hl & 4) != 0;
    const bool g8 = (hl & 8) != 0;

    // float4 index: row*16 + hl -> (base + 2u + h)*16 + hl = base*16 + 32u + lane
    const float4* __restrict__ nvec = noise4 + (size_t)base * 16 + lane;
    float4*       __restrict__ ovec = out4   + (size_t)base * 16 + lane;

    // ---- front-batch the 4 noise vector loads (MLP) ----
    float4 xs[BATCH / 2];
    #pragma unroll
    for (int u = 0; u < BATCH / 2; u++) xs[u] = nvec[32 * u];

    #pragma unroll
    for (int u = 0; u < BATCH / 2; u++) {
        // ---- direct param load: uniform per half, adjacent rows -> 1 sector ----
        const float4 p = params4[base + 2 * u + h];

        const float energy = p.y;
        const float tilt   = p.z * 2.0f - 1.0f;

        // Replicate XLA's separate-op fp32 rounding at the int-trunc boundary:
        const float bandwidth = __fadd_rn(0.05f, __fmul_rn(p.w, 0.95f));
        const float dval      = __fmul_rn(64.0f,
                                  __fadd_rn(0.5f, __fmul_rn(0.5f, bandwidth)));
        int dj = (int)dval;
        dj = min(max(dj, 1), 480);

        const float attack_samples =
            fmaxf((0.0005f + p.x * 0.0495f) * 16000.0f, 1.0f);
        const float rj = __expf(-1.0f / attack_samples);

        const float4 x = xs[u];

        // ---- envelope: env = energy * r^(4*hl), then * r^k ----
        const float r2 = rj * rj;
        const float r4 = r2 * r2;     // r^4  (bit 0 of hl)
        const float w2 = r4 * r4;     // r^8  (bit 1)
        const float w4 = w2 * w2;     // r^16 (bit 2)
        const float w8 = w4 * w4;     // r^32 (bit 3)
        float env = energy;
        if (g1) env *= r4;
        if (g2) env *= w2;
        if (g4) env *= w4;
        if (g8) env *= w8;            // env = energy * r^(4*hl)
        const float e1 = env * rj;
        const float e2 = e1  * rj;
        const float e3 = e2  * rj;

        const float b0 = x.x * env;
        const float b1 = x.y * e1;
        const float b2 = x.z * e2;
        const float b3 = x.w * e3;

        // ---- comb tap: sample s=s0+k taps sample s-dj (pre-tap burst value,
        //      since s-dj <= 30 < dj). Hoisted index math:
        const int ibase = s0 - dj;                 // idx_k = ibase + k
        const int c0    = (-dj) & 3;               // comp_k = (c0 + k) & 3

        float y0 = b0, y1 = b1, y2 = b2, y3 = b3;
        #pragma unroll
        for (int k = 0; k < 4; k++) {
            const int   idx  = ibase + k;
            const int   sl   = (idx >> 2) & 15;          // source sub-lane
            const int   comp = (c0 + k) & 3;             // uniform per half
            const float lo   = (comp & 1) ? b1 : b0;
            const float hi   = (comp & 1) ? b3 : b2;
            const float vk   = (comp & 2) ? hi : lo;     // own b[comp]
            const float src  = __shfl_sync(FULLM, vk, sl, 16);
            const float tap  = (idx >= 0) ? tilt * src : 0.0f;
            if (k == 0) y0 = b0 + tap;
            if (k == 1) y1 = b1 + tap;
            if (k == 2) y2 = b2 + tap;
            if (k == 3) y3 = b3 + tap;
        }

        // ---- RMS: 16-lane butterfly (4 shfls serve BOTH rows) ----
        float ss = fmaf(y0, y0, y1 * y1) + fmaf(y2, y2, y3 * y3);
        ss += __shfl_xor_sync(FULLM, ss, 1);
        ss += __shfl_xor_sync(FULLM, ss, 2);
        ss += __shfl_xor_sync(FULLM, ss, 4);
        ss += __shfl_xor_sync(FULLM, ss, 8);

        const float inv = rsqrtf(fmaf(ss, (1.0f / 64.0f), 1e-5f));

        ovec[32 * u] = make_float4(y0 * inv, y1 * inv, y2 * inv, y3 * inv);
    }
}

extern "C" void kernel_launch(void* const* d_in, const int* in_sizes, int n_in,
                              void* d_out, int out_size)
{
    const float4* params = (const float4*)d_in[0];  // [32,2000,4]
    const float4* noise  = (const float4*)d_in[1];  // [32,2000,64] as float4
    float4* out          = (float4*)d_out;          // [32, 2000*64] as float4

    (void)in_sizes; (void)n_in; (void)out_size;

    // 8000 warps, 8 rows each: 1000 blocks x 256 threads
    const int threads = 256;
    const int blocks  = (NWARPS * 32) / threads;    // 1000
    transient_comb_kernel<<<blocks, threads>>>(params, noise, out);
}